// round 5
// baseline (speedup 1.0000x reference)
#include <cuda_runtime.h>

// y[b,c] = b_fc[c] + dot(h[b,0,:], V[c,:]),  V = W_fc @ W_emb  ([2,768])
// (TreeLSTM scan in the reference is dead code; adj and recurrent weights unused.)
// B=32, N=128, FI=768, FO=128.
//
// Single fused kernel: 24 producer blocks build V, 32 consumer blocks (one
// per batch) spin on an arrival counter, then contract with h[b,0,:].
// All 56 blocks are co-resident in wave 1 (<=1 block/SM), so the spin is safe.

#define B_  32
#define N_  128
#define FI_ 768
#define FO_ 128
#define NPROD_ 24
#define NBLK_  (NPROD_ + B_)

__device__ float    g_V[2][FI_];
__device__ unsigned g_arrive = 0;   // producers arrived
__device__ unsigned g_done   = 0;   // consumers finished

__global__ __launch_bounds__(256, 1)
void rvnn_fused(const float* __restrict__ h,      // [B,N,FI]
                const float* __restrict__ W_emb,  // [FO,FI]
                const float* __restrict__ W_fc,   // [2,FO]
                const float* __restrict__ b_fc,   // [2]
                float* __restrict__ y)            // [B,2]
{
    const int bid = blockIdx.x;
    const int t   = threadIdx.x;

    if (bid < NPROD_) {
        // ---- Producer: V[c, bid*32 .. bid*32+31] ----
        const int fl = t & 31;          // f within block
        const int g  = t >> 5;          // o-chunk 0..7 (16 o's each)
        const int f  = bid * 32 + fl;

        float a0 = 0.0f, a1 = 0.0f;
        #pragma unroll
        for (int j = 0; j < 16; ++j) {
            const int o = g * 16 + j;
            float w = __ldg(&W_emb[(size_t)o * FI_ + f]);   // coalesced in f
            a0 = fmaf(__ldg(&W_fc[o]),       w, a0);
            a1 = fmaf(__ldg(&W_fc[FO_ + o]), w, a1);
        }

        __shared__ float sp0[8][32], sp1[8][32];
        sp0[g][fl] = a0;
        sp1[g][fl] = a1;
        __syncthreads();

        if (t < 32) {
            float s = 0.0f;
            #pragma unroll
            for (int k = 0; k < 8; ++k) s += sp0[k][t];
            g_V[0][bid * 32 + t] = s;
        } else if (t < 64) {
            const int l = t - 32;
            float s = 0.0f;
            #pragma unroll
            for (int k = 0; k < 8; ++k) s += sp1[k][l];
            g_V[1][bid * 32 + l] = s;
        }
        __syncthreads();
        if (t == 0) {
            __threadfence();                 // V visible before arrive
            atomicAdd(&g_arrive, 1u);
        }
    } else {
        // ---- Consumer: y[b,:] for b = bid - NPROD_ ----
        const int b    = bid - NPROD_;
        const int warp = t >> 5;            // 0..7
        const int lane = t & 31;

        // Issue h loads FIRST: their DRAM latency overlaps producer work.
        float4 hv = make_float4(0.f, 0.f, 0.f, 0.f);
        const float4* hrow = reinterpret_cast<const float4*>(h + (size_t)b * N_ * FI_);
        if (t < FI_ / 4)
            hv = __ldg(&hrow[t]);

        // Wait for all producers.
        __shared__ int s_ready;
        if (t == 0) {
            while (atomicAdd(&g_arrive, 0u) < NPROD_) { /* spin */ }
            __threadfence();                 // acquire: order V reads after
            s_ready = 1;
        }
        __syncthreads();
        (void)s_ready;

        float a0 = 0.0f, a1 = 0.0f;
        if (t < FI_ / 4) {
            float4 v0 = *reinterpret_cast<const float4*>(&g_V[0][t * 4]);
            float4 v1 = *reinterpret_cast<const float4*>(&g_V[1][t * 4]);
            a0 = fmaf(hv.x, v0.x, fmaf(hv.y, v0.y, fmaf(hv.z, v0.z, hv.w * v0.w)));
            a1 = fmaf(hv.x, v1.x, fmaf(hv.y, v1.y, fmaf(hv.z, v1.z, hv.w * v1.w)));
        }

        #pragma unroll
        for (int off = 16; off > 0; off >>= 1) {
            a0 += __shfl_down_sync(0xffffffffu, a0, off);
            a1 += __shfl_down_sync(0xffffffffu, a1, off);
        }

        __shared__ float w0[8], w1[8];
        if (lane == 0) { w0[warp] = a0; w1[warp] = a1; }
        __syncthreads();

        if (t == 0) {
            float s0 = 0.0f, s1 = 0.0f;
            #pragma unroll
            for (int k = 0; k < 6; ++k) { s0 += w0[k]; s1 += w1[k]; }  // warps 6,7 idle in compute
            y[b * 2 + 0] = s0 + b_fc[0];
            y[b * 2 + 1] = s1 + b_fc[1];

            // Last consumer resets counters for the next graph replay.
            unsigned prev = atomicAdd(&g_done, 1u);
            if (prev == B_ - 1) {
                atomicExch(&g_arrive, 0u);
                atomicExch(&g_done, 0u);
            }
        }
    }
}

extern "C" void kernel_launch(void* const* d_in, const int* in_sizes, int n_in,
                              void* d_out, int out_size)
{
    // metadata order: h, adj, W_emb, W_ioux, b_ioux, W_iouh, b_iouh,
    //                 W_coux, b_coux, W_couh, b_couh, W_fc, b_fc
    const float* h     = (const float*)d_in[0];
    const float* W_emb = (const float*)d_in[2];
    const float* W_fc  = (const float*)d_in[11];
    const float* b_fc  = (const float*)d_in[12];
    float* y = (float*)d_out;

    rvnn_fused<<<NBLK_, 256>>>(h, W_emb, W_fc, b_fc, y);
}